// round 1
// baseline (speedup 1.0000x reference)
#include <cuda_runtime.h>
#include <cstdint>
#include <cstddef>

#define B_ 2
#define S_ 2048
#define D_ 64
#define H_ 8

#define TM 128   // rows per CTA
#define TN 64    // t-columns per main-loop iteration
#define NTHREADS 128

// smem pads (in 32-bit words): keep 16B row alignment, conflict-free mma fragment loads
#define PQ 68
#define PK 68
#define PV 72
#define PP 68

#define SMEM_WORDS (TM*PQ + TN*PK + TN*PV + TM*PP)
#define SMEM_BYTES (SMEM_WORDS * 4)

__device__ __forceinline__ uint32_t f2tf(float x) {
    uint32_t r;
    asm("cvt.rna.tf32.f32 %0, %1;" : "=r"(r) : "f"(x));
    return r;
}

__device__ __forceinline__ void mma_tf32(float c[4],
                                         uint32_t a0, uint32_t a1, uint32_t a2, uint32_t a3,
                                         uint32_t b0, uint32_t b1) {
    asm volatile(
        "mma.sync.aligned.m16n8k8.row.col.f32.tf32.tf32.f32 "
        "{%0,%1,%2,%3}, {%4,%5,%6,%7}, {%8,%9}, {%0,%1,%2,%3};\n"
        : "+f"(c[0]), "+f"(c[1]), "+f"(c[2]), "+f"(c[3])
        : "r"(a0), "r"(a1), "r"(a2), "r"(a3), "r"(b0), "r"(b1));
}

__global__ void __launch_bounds__(NTHREADS, 2)
attn_bias_kernel(const float* __restrict__ x1,
                 const float* __restrict__ x2,
                 const float* __restrict__ x3,
                 const float* __restrict__ x4,
                 float* __restrict__ out) {
    const int mt = blockIdx.x;   // 0..15   (row tile)
    const int h  = blockIdx.y;   // 0..7
    const int b  = blockIdx.z;   // 0..1

    const int tid  = threadIdx.x;
    const int warp = tid >> 5;
    const int lane = tid & 31;
    const int r = lane >> 2;     // group id (row within 8)
    const int q = lane & 3;      // thread within group

    extern __shared__ uint32_t smem[];
    uint32_t* sQ = smem;               // [TM][PQ]  tf32
    uint32_t* sK = sQ + TM * PQ;       // [TN][PK]  tf32
    uint32_t* sV = sK + TN * PK;       // [TN][PV]  tf32
    uint32_t* sP = sV + TN * PV;       // [TM][PP]  tf32

    // ---- load Q tile (TM x 64) once ----
    const float* qbase = x1 + ((size_t)b * S_ + (size_t)mt * TM) * D_;
    #pragma unroll
    for (int i = tid; i < TM * (D_ / 4); i += NTHREADS) {
        int row = i >> 4;       // 16 float4 per row
        int c4  = i & 15;
        float4 v = *reinterpret_cast<const float4*>(qbase + row * D_ + c4 * 4);
        uint32_t* dst = sQ + row * PQ + c4 * 4;
        dst[0] = f2tf(v.x); dst[1] = f2tf(v.y); dst[2] = f2tf(v.z); dst[3] = f2tf(v.w);
    }

    float accO[2][8][4];
    #pragma unroll
    for (int mf = 0; mf < 2; ++mf)
        #pragma unroll
        for (int n = 0; n < 8; ++n)
            #pragma unroll
            for (int j = 0; j < 4; ++j) accO[mf][n][j] = 0.0f;
    float lsum[2][2] = {{0.0f, 0.0f}, {0.0f, 0.0f}};

    const float* kbase = x2 + (size_t)b * S_ * D_;
    const float* vbase = x4 + (size_t)b * S_ * D_;
    const float* biasbase = x3 + (((size_t)b * H_ + h) * S_ + (size_t)mt * TM) * S_;

    const int R0 = warp * 32;       // this warp's first row in the CTA tile
    const int R1 = warp * 32 + 16;

    for (int t0 = 0; t0 < S_; t0 += TN) {
        __syncthreads();   // protect sK/sV (and sP) from previous iteration's readers

        // ---- load K,V tiles (TN x 64 each) ----
        #pragma unroll
        for (int i = tid; i < TN * (D_ / 4); i += NTHREADS) {
            int row = i >> 4;
            int c4  = i & 15;
            float4 kv = *reinterpret_cast<const float4*>(kbase + (size_t)(t0 + row) * D_ + c4 * 4);
            uint32_t* dk = sK + row * PK + c4 * 4;
            dk[0] = f2tf(kv.x); dk[1] = f2tf(kv.y); dk[2] = f2tf(kv.z); dk[3] = f2tf(kv.w);
            float4 vv = *reinterpret_cast<const float4*>(vbase + (size_t)(t0 + row) * D_ + c4 * 4);
            uint32_t* dv = sV + row * PV + c4 * 4;
            dv[0] = f2tf(vv.x); dv[1] = f2tf(vv.y); dv[2] = f2tf(vv.z); dv[3] = f2tf(vv.w);
        }
        __syncthreads();

        // ---- S = Q @ K^T  (per warp: 32 rows x 64 cols) ----
        float c[2][8][4];
        #pragma unroll
        for (int mf = 0; mf < 2; ++mf)
            #pragma unroll
            for (int n = 0; n < 8; ++n)
                #pragma unroll
                for (int j = 0; j < 4; ++j) c[mf][n][j] = 0.0f;

        #pragma unroll
        for (int k = 0; k < 8; ++k) {
            uint32_t a0[4], a1[4];
            a0[0] = sQ[(R0 + r) * PQ + 8 * k + q];
            a0[1] = sQ[(R0 + r + 8) * PQ + 8 * k + q];
            a0[2] = sQ[(R0 + r) * PQ + 8 * k + q + 4];
            a0[3] = sQ[(R0 + r + 8) * PQ + 8 * k + q + 4];
            a1[0] = sQ[(R1 + r) * PQ + 8 * k + q];
            a1[1] = sQ[(R1 + r + 8) * PQ + 8 * k + q];
            a1[2] = sQ[(R1 + r) * PQ + 8 * k + q + 4];
            a1[3] = sQ[(R1 + r + 8) * PQ + 8 * k + q + 4];
            #pragma unroll
            for (int n = 0; n < 8; ++n) {
                uint32_t b0 = sK[(8 * n + r) * PK + 8 * k + q];
                uint32_t b1 = sK[(8 * n + r) * PK + 8 * k + q + 4];
                mma_tf32(c[0][n], a0[0], a0[1], a0[2], a0[3], b0, b1);
                mma_tf32(c[1][n], a1[0], a1[1], a1[2], a1[3], b0, b1);
            }
        }

        // ---- logits -> exp -> P (smem, tf32), accumulate row sums ----
        #pragma unroll
        for (int mf = 0; mf < 2; ++mf) {
            const int R = (mf == 0) ? R0 : R1;
            const float* brow0 = biasbase + (size_t)(R + r) * S_ + t0;
            const float* brow1 = biasbase + (size_t)(R + r + 8) * S_ + t0;
            #pragma unroll
            for (int n = 0; n < 8; ++n) {
                float2 bb0 = *reinterpret_cast<const float2*>(brow0 + 8 * n + 2 * q);
                float2 bb1 = *reinterpret_cast<const float2*>(brow1 + 8 * n + 2 * q);
                float p0 = __expf(fmaf(c[mf][n][0], 0.125f, bb0.x));
                float p1 = __expf(fmaf(c[mf][n][1], 0.125f, bb0.y));
                float p2 = __expf(fmaf(c[mf][n][2], 0.125f, bb1.x));
                float p3 = __expf(fmaf(c[mf][n][3], 0.125f, bb1.y));
                lsum[mf][0] += p0 + p1;
                lsum[mf][1] += p2 + p3;
                sP[(R + r) * PP + 8 * n + 2 * q]     = f2tf(p0);
                sP[(R + r) * PP + 8 * n + 2 * q + 1] = f2tf(p1);
                sP[(R + r + 8) * PP + 8 * n + 2 * q]     = f2tf(p2);
                sP[(R + r + 8) * PP + 8 * n + 2 * q + 1] = f2tf(p3);
            }
        }
        __syncwarp();   // each warp reads only its own rows of sP

        // ---- O += P @ V ----
        #pragma unroll
        for (int k = 0; k < 8; ++k) {
            uint32_t a0[4], a1[4];
            a0[0] = sP[(R0 + r) * PP + 8 * k + q];
            a0[1] = sP[(R0 + r + 8) * PP + 8 * k + q];
            a0[2] = sP[(R0 + r) * PP + 8 * k + q + 4];
            a0[3] = sP[(R0 + r + 8) * PP + 8 * k + q + 4];
            a1[0] = sP[(R1 + r) * PP + 8 * k + q];
            a1[1] = sP[(R1 + r + 8) * PP + 8 * k + q];
            a1[2] = sP[(R1 + r) * PP + 8 * k + q + 4];
            a1[3] = sP[(R1 + r + 8) * PP + 8 * k + q + 4];
            #pragma unroll
            for (int n = 0; n < 8; ++n) {
                uint32_t b0 = sV[(8 * k + q) * PV + 8 * n + r];
                uint32_t b1 = sV[(8 * k + q + 4) * PV + 8 * n + r];
                mma_tf32(accO[0][n], a0[0], a0[1], a0[2], a0[3], b0, b1);
                mma_tf32(accO[1][n], a1[0], a1[1], a1[2], a1[3], b0, b1);
            }
        }
    }

    // ---- finalize: reduce row sums across the quad, divide, store ----
    #pragma unroll
    for (int mf = 0; mf < 2; ++mf)
        #pragma unroll
        for (int j = 0; j < 2; ++j) {
            lsum[mf][j] += __shfl_xor_sync(0xffffffffu, lsum[mf][j], 1);
            lsum[mf][j] += __shfl_xor_sync(0xffffffffu, lsum[mf][j], 2);
        }

    float inv[2][2];
    inv[0][0] = 1.0f / lsum[0][0]; inv[0][1] = 1.0f / lsum[0][1];
    inv[1][0] = 1.0f / lsum[1][0]; inv[1][1] = 1.0f / lsum[1][1];

    float* obase = out + (((size_t)b * H_ + h) * S_ + (size_t)mt * TM) * D_;
    #pragma unroll
    for (int mf = 0; mf < 2; ++mf) {
        const int R = (mf == 0) ? R0 : R1;
        #pragma unroll
        for (int n = 0; n < 8; ++n) {
            float2 v0 = make_float2(accO[mf][n][0] * inv[mf][0], accO[mf][n][1] * inv[mf][0]);
            float2 v1 = make_float2(accO[mf][n][2] * inv[mf][1], accO[mf][n][3] * inv[mf][1]);
            *reinterpret_cast<float2*>(obase + (size_t)(R + r) * D_ + 8 * n + 2 * q) = v0;
            *reinterpret_cast<float2*>(obase + (size_t)(R + r + 8) * D_ + 8 * n + 2 * q) = v1;
        }
    }
}

extern "C" void kernel_launch(void* const* d_in, const int* in_sizes, int n_in,
                              void* d_out, int out_size) {
    (void)in_sizes; (void)n_in; (void)out_size;
    const float* x1 = (const float*)d_in[0];
    const float* x2 = (const float*)d_in[1];
    const float* x3 = (const float*)d_in[2];
    const float* x4 = (const float*)d_in[3];
    float* out = (float*)d_out;

    cudaFuncSetAttribute(attn_bias_kernel,
                         cudaFuncAttributeMaxDynamicSharedMemorySize, SMEM_BYTES);

    dim3 grid(S_ / TM, H_, B_);   // 16 x 8 x 2 = 256 CTAs
    attn_bias_kernel<<<grid, NTHREADS, SMEM_BYTES>>>(x1, x2, x3, x4, out);
}